// round 16
// baseline (speedup 1.0000x reference)
#include <cuda_runtime.h>
#include <cuda_fp16.h>
#include <cstdint>

#define NB   64
#define NC   256
#define NCI  128
#define NTOK 256
#define NH   64

// -------------------- device scratch --------------------
__device__ __half g_xpt [NB * NTOK * NC];   // pooled fp16 [b][tok][c]  (GEMM operand)
__device__ __half g_xpc [NB * NC * NTOK];   // pooled fp16 [b][c][tok]  (residual, coalesced)
__device__ __half g_Wch [256 * NC];         // theta|phi weights fp16 [r][c]
__device__ __half g_gwh [NCI * NC];         // fp16 [cc][c]
__device__ __half g_owh [NC * NCI];         // fp16 [C][cc]
__device__ float  g_btp [256];              // theta_b|phi_b fp32
__device__ __half g_proj[NB * NTOK * 256];  // [tok][r] (theta 0-127 | phi 128-255)
__device__ __half g_g   [NB * NCI * NTOK];  // [cc][j]
__device__ __half g_agg [NB * NTOK * NCI];  // [i][cc]

// -------------------- helpers --------------------
__device__ __forceinline__ void mma_f16(float (&c)[4],
                                        uint32_t a0, uint32_t a1, uint32_t a2, uint32_t a3,
                                        uint32_t b0, uint32_t b1) {
    asm volatile(
        "mma.sync.aligned.m16n8k16.row.col.f32.f16.f16.f32 "
        "{%0,%1,%2,%3},{%4,%5,%6,%7},{%8,%9},{%0,%1,%2,%3};\n"
        : "+f"(c[0]), "+f"(c[1]), "+f"(c[2]), "+f"(c[3])
        : "r"(a0), "r"(a1), "r"(a2), "r"(a3), "r"(b0), "r"(b1));
}
#define LDSM4(r0, r1, r2, r3, a) \
    asm volatile("ldmatrix.sync.aligned.m8n8.x4.shared.b16 {%0,%1,%2,%3}, [%4];" \
                 : "=r"(r0), "=r"(r1), "=r"(r2), "=r"(r3) : "r"(a))
#define CPA(dst, src) asm volatile("cp.async.cg.shared.global [%0], [%1], 16;" :: "r"(dst), "l"(src))
#define CPC()         asm volatile("cp.async.commit_group;")
#define CPW(n)        asm volatile("cp.async.wait_group %0;" :: "n"(n))

// -------------------- fused pool + weight prep --------------------
__global__ void __launch_bounds__(256) pool_prep_kernel(
    const float* __restrict__ x,
    const float* __restrict__ tw, const float* __restrict__ tb,
    const float* __restrict__ pw, const float* __restrict__ pb,
    const float* __restrict__ gw, const float* __restrict__ ow) {
    if (blockIdx.x < 512) {
        __shared__ float tile[32][257];
        int b = blockIdx.x >> 3, c0 = (blockIdx.x & 7) << 5;
        int t = threadIdx.x;
        int ph = t >> 4, pw2 = t & 15;
        for (int ci = 0; ci < 32; ci++) {
            int c = c0 + ci;
            const float* base = x + (((long)b * NC + c) * NH + ph * 4) * NH + pw2 * 4;
            float4 v0 = *(const float4*)(base);
            float4 v1 = *(const float4*)(base + NH);
            float4 v2 = *(const float4*)(base + 2 * NH);
            float4 v3 = *(const float4*)(base + 3 * NH);
            float s = ((v0.x + v0.y + v0.z + v0.w) + (v1.x + v1.y + v1.z + v1.w)
                     + (v2.x + v2.y + v2.z + v2.w) + (v3.x + v3.y + v3.z + v3.w)) * 0.0625f;
            tile[ci][t] = s;
            g_xpc[((long)b * NC + c) * NTOK + t] = __float2half_rn(s);  // coalesced over t
        }
        __syncthreads();
#pragma unroll
        for (int rep = 0; rep < 8; rep++) {
            int u = rep * 256 + t;
            int tok = u >> 3, cq = (u & 7) << 2;
            __half2 h0 = __floats2half2_rn(tile[cq][tok],     tile[cq + 1][tok]);
            __half2 h1 = __floats2half2_rn(tile[cq + 2][tok], tile[cq + 3][tok]);
            __half2* dst = (__half2*)&g_xpt[((long)b * NTOK + tok) * NC + c0 + cq];
            dst[0] = h0; dst[1] = h1;
        }
    } else {
        int idx = (blockIdx.x - 512) * 256 + threadIdx.x;
        if (idx < 65536) {
            int r = idx >> 8;
            g_Wch[idx] = __float2half_rn((r < 128) ? tw[idx] : pw[idx - 32768]);
            if (idx < 256) g_btp[idx] = (idx < 128) ? tb[idx] : pb[idx - 128];
        } else if (idx < 98304) {
            int j = idx - 65536;
            g_gwh[j] = __float2half_rn(gw[j]);
        } else {
            int j = idx - 98304;
            g_owh[j] = __float2half_rn(ow[j]);
        }
    }
}

// -------------------- fp16 GEMM core: BM=128, BN=128, BK=32, ldmatrix --------------------
// EPI 1: fp16 +bias[n]  2: fp16 +bias[m]
// EPI 3: fp32 +bias[m] + resid(fp16 [c][tok], coalesced), nearest 4x4 upsample -> dout
template<int EPI>
__device__ __forceinline__ void hgemm_core(
    const __half* __restrict__ A, const __half* __restrict__ B, void* __restrict__ Cg,
    int lda, int ldb, int ldc, int K, int m0, int n0, int b,
    const float* __restrict__ bias, const __half* __restrict__ residh,
    float* __restrict__ dout, __half* smem)
{
    constexpr int SKB  = 80;
    constexpr int AB   = 128 * SKB;
    constexpr int STGB = 2 * AB;

    uint32_t su = (uint32_t)__cvta_generic_to_shared(smem);
    int tid = threadIdx.x;
    int lane = tid & 31, wid = tid >> 5;
    int wm = (wid & 3) << 5;
    int wn = (wid >> 2) << 6;
    int gr = lane >> 2, tc = lane & 3;

    float acc[2][8][4] = {};
    int nk = K >> 5;

    uint32_t aAddr = su + (wm + (lane & 15)) * SKB + ((lane >> 4) << 4);
    uint32_t bAddr = su + AB + (wn + (lane & 7) + ((lane >> 4) << 3)) * SKB
                   + (((lane >> 3) & 1) << 4);

    int rS = tid >> 2, cS = tid & 3;
    auto issue = [&](int slot, int t) {
        int k0 = t << 5;
        uint32_t base = su + slot * STGB;
        CPA(base + rS * SKB + cS * 16,        A + (long)(m0 + rS) * lda + k0 + cS * 8);
        CPA(base + (rS + 64) * SKB + cS * 16, A + (long)(m0 + rS + 64) * lda + k0 + cS * 8);
        uint32_t bb = base + AB;
        CPA(bb + rS * SKB + cS * 16,          B + (long)(n0 + rS) * ldb + k0 + cS * 8);
        CPA(bb + (rS + 64) * SKB + cS * 16,   B + (long)(n0 + rS + 64) * ldb + k0 + cS * 8);
        CPC();
    };

    issue(0, 0); issue(1, 1); issue(2, 2);

    for (int t = 0; t < nk; t++) {
        CPW(2);
        __syncthreads();
        if (t + 3 < nk) issue((t + 3) & 3, t + 3);
        else            CPC();
        uint32_t so = (uint32_t)(t & 3) * STGB;
#pragma unroll
        for (int ks = 0; ks < 2; ks++) {
            uint32_t ko = ks << 5;
            uint32_t fa[2][4];
            LDSM4(fa[0][0], fa[0][1], fa[0][2], fa[0][3], aAddr + so + ko);
            LDSM4(fa[1][0], fa[1][1], fa[1][2], fa[1][3], aAddr + so + ko + 16 * SKB);
#pragma unroll
            for (int p = 0; p < 4; p++) {
                uint32_t b0, b1, b2, b3;
                LDSM4(b0, b1, b2, b3, bAddr + so + ko + p * 16 * SKB);
                mma_f16(acc[0][2 * p],     fa[0][0], fa[0][1], fa[0][2], fa[0][3], b0, b1);
                mma_f16(acc[1][2 * p],     fa[1][0], fa[1][1], fa[1][2], fa[1][3], b0, b1);
                mma_f16(acc[0][2 * p + 1], fa[0][0], fa[0][1], fa[0][2], fa[0][3], b2, b3);
                mma_f16(acc[1][2 * p + 1], fa[1][0], fa[1][1], fa[1][2], fa[1][3], b2, b3);
            }
        }
    }

    if (EPI == 1 || EPI == 2) {
        __half* Cb = (__half*)Cg;
#pragma unroll
        for (int mt = 0; mt < 2; mt++) {
            int r0 = m0 + wm + (mt << 4) + gr;
            float bm0 = 0.f, bm1 = 0.f;
            if (EPI == 2) { bm0 = bias[r0]; bm1 = bias[r0 + 8]; }
#pragma unroll
            for (int nt = 0; nt < 8; nt++) {
                int cn = n0 + wn + (nt << 3) + (tc << 1);
                float bn0 = 0.f, bn1 = 0.f;
                if (EPI == 1) { bn0 = bias[cn]; bn1 = bias[cn + 1]; }
                *(__half2*)(Cb + (long)r0 * ldc + cn) =
                    __floats2half2_rn(acc[mt][nt][0] + bm0 + bn0, acc[mt][nt][1] + bm0 + bn1);
                *(__half2*)(Cb + (long)(r0 + 8) * ldc + cn) =
                    __floats2half2_rn(acc[mt][nt][2] + bm1 + bn0, acc[mt][nt][3] + bm1 + bn1);
            }
        }
    } else {
        // EPI 3: residual from xpc fp16 [c][tok] (contiguous over tok)
#pragma unroll
        for (int mt = 0; mt < 2; mt++) {
#pragma unroll
            for (int rr = 0; rr < 2; rr++) {
                int c = m0 + wm + (mt << 4) + gr + (rr << 3);
                float bi = bias[c];
                const __half* rrow = residh + ((long)b * NC + c) * NTOK;
                float* orow = dout + ((long)b * NC + c) * (NH * NH);
#pragma unroll
                for (int nt = 0; nt < 8; nt++) {
                    int tok0 = n0 + wn + (nt << 3) + (tc << 1);
                    __half2 rh = *(const __half2*)(rrow + tok0);
                    float r2[2] = {__half2float(rh.x), __half2float(rh.y)};
#pragma unroll
                    for (int jj = 0; jj < 2; jj++) {
                        int tok = tok0 + jj;
                        float v = acc[mt][nt][rr * 2 + jj] + bi + r2[jj];
                        int ph = tok >> 4, pw = tok & 15;
                        float* o = orow + (ph * 4) * NH + pw * 4;
                        float4 f = make_float4(v, v, v, v);
                        *(float4*)(o)          = f;
                        *(float4*)(o + NH)     = f;
                        *(float4*)(o + 2 * NH) = f;
                        *(float4*)(o + 3 * NH) = f;
                    }
                }
            }
        }
    }
}

template<int EPI>
__global__ void __launch_bounds__(256, 2) hgemm_k(
    const __half* __restrict__ Ag, const __half* __restrict__ Bg, void* __restrict__ Cg,
    int lda, int ldb, int ldc, int K,
    long aB, long bB, long cB,
    const float* __restrict__ bias, const __half* __restrict__ residh, float* __restrict__ dout)
{
    extern __shared__ __half smem[];
    int b = blockIdx.z;
    char* Cp = (char*)Cg + (long)b * cB;
    hgemm_core<EPI>(Ag + (long)b * aB, Bg + (long)b * bB, (void*)Cp,
                    lda, ldb, ldc, K, blockIdx.y << 7, blockIdx.x << 7, b,
                    bias, residh, dout, smem);
}

// -------------------- fused attention: logits + softmax + agg --------------------
__global__ void __launch_bounds__(256) attn_kernel(
    const __half* __restrict__ proj, const __half* __restrict__ gg,
    __half* __restrict__ agg)
{
    constexpr int SKB  = 80;
    constexpr int A1B  = 64 * SKB;
    constexpr int B1B  = 256 * SKB;
    constexpr int STG1 = A1B + B1B;           // 25600
    constexpr int ATTN = 4 * STG1;            // 102400
    constexpr int ROWB = 528;
    constexpr int GOFF = ATTN + 64 * ROWB;

    extern __shared__ __half smem[];
    __shared__ float red[4][64];
    uint32_t su = (uint32_t)__cvta_generic_to_shared(smem);
    char* smc = (char*)smem;

    int b = blockIdx.y;
    int m0 = blockIdx.x << 6;
    const __half* theta = proj + (long)b * 65536;
    const __half* phi   = theta + 128;
    const __half* gb    = gg + (long)b * 32768;

    int tid = threadIdx.x, lane = tid & 31, wid = tid >> 5;
    int gr = lane >> 2, tc = lane & 3;
    int wm1 = (wid & 1) << 5;
    int wn1 = (wid >> 1) << 6;
    int wnid = wid >> 1;

    int rA = tid >> 2, cA = tid & 3;
#pragma unroll
    for (int t = 0; t < 4; t++) {
        uint32_t base = su + t * STG1;
        CPA(base + rA * SKB + cA * 16, theta + (long)(m0 + rA) * 256 + t * 32 + cA * 8);
#pragma unroll
        for (int it = 0; it < 4; it++) {
            int row = rA + it * 64;
            CPA(base + A1B + row * SKB + cA * 16, phi + (long)row * 256 + t * 32 + cA * 8);
        }
#pragma unroll
        for (int k = 0; k < 4; k++) {
            int u = tid + k * 256;
            int grow = t * 32 + (u >> 5);
            int gch = u & 31;
            CPA(su + GOFF + grow * ROWB + gch * 16, gb + (long)grow * 256 + gch * 8);
        }
        CPC();
    }

    uint32_t aA1 = su + (wm1 + (lane & 15)) * SKB + ((lane >> 4) << 4);
    uint32_t bA1 = su + A1B + (wn1 + (lane & 7) + ((lane >> 4) << 3)) * SKB
                 + (((lane >> 3) & 1) << 4);

    float acc[2][8][4] = {};
#pragma unroll
    for (int t = 0; t < 4; t++) {
        if (t == 0)      { CPW(3); }
        else if (t == 1) { CPW(2); }
        else if (t == 2) { CPW(1); }
        else             { CPW(0); }
        __syncthreads();
        uint32_t so = (uint32_t)t * STG1;
#pragma unroll
        for (int ks = 0; ks < 2; ks++) {
            uint32_t ko = ks << 5;
            uint32_t fa[2][4];
            LDSM4(fa[0][0], fa[0][1], fa[0][2], fa[0][3], aA1 + so + ko);
            LDSM4(fa[1][0], fa[1][1], fa[1][2], fa[1][3], aA1 + so + ko + 16 * SKB);
#pragma unroll
            for (int p = 0; p < 4; p++) {
                uint32_t b0, b1, b2, b3;
                LDSM4(b0, b1, b2, b3, bA1 + so + ko + p * 16 * SKB);
                mma_f16(acc[0][2 * p],     fa[0][0], fa[0][1], fa[0][2], fa[0][3], b0, b1);
                mma_f16(acc[1][2 * p],     fa[1][0], fa[1][1], fa[1][2], fa[1][3], b0, b1);
                mma_f16(acc[0][2 * p + 1], fa[0][0], fa[0][1], fa[0][2], fa[0][3], b2, b3);
                mma_f16(acc[1][2 * p + 1], fa[1][0], fa[1][1], fa[1][2], fa[1][3], b2, b3);
            }
        }
    }

    // ---- softmax over j ----
    float rmx[2][2];
#pragma unroll
    for (int mt = 0; mt < 2; mt++)
#pragma unroll
        for (int rh = 0; rh < 2; rh++) {
            float m = -1e30f;
#pragma unroll
            for (int nt = 0; nt < 8; nt++)
                m = fmaxf(m, fmaxf(acc[mt][nt][rh * 2], acc[mt][nt][rh * 2 + 1]));
            m = fmaxf(m, __shfl_xor_sync(0xffffffffu, m, 1));
            m = fmaxf(m, __shfl_xor_sync(0xffffffffu, m, 2));
            rmx[mt][rh] = m;
        }
    if (tc == 0) {
#pragma unroll
        for (int mt = 0; mt < 2; mt++) {
            red[wnid][wm1 + (mt << 4) + gr]     = rmx[mt][0];
            red[wnid][wm1 + (mt << 4) + gr + 8] = rmx[mt][1];
        }
    }
    __syncthreads();
#pragma unroll
    for (int mt = 0; mt < 2; mt++)
#pragma unroll
        for (int rh = 0; rh < 2; rh++) {
            int row = wm1 + (mt << 4) + gr + rh * 8;
            rmx[mt][rh] = fmaxf(fmaxf(red[0][row], red[1][row]),
                                fmaxf(red[2][row], red[3][row]));
        }
    __syncthreads();

    float rsum[2][2];
#pragma unroll
    for (int mt = 0; mt < 2; mt++)
#pragma unroll
        for (int rh = 0; rh < 2; rh++) {
            float s = 0.f;
#pragma unroll
            for (int nt = 0; nt < 8; nt++) {
                acc[mt][nt][rh * 2]     = __expf(acc[mt][nt][rh * 2]     - rmx[mt][rh]);
                acc[mt][nt][rh * 2 + 1] = __expf(acc[mt][nt][rh * 2 + 1] - rmx[mt][rh]);
                s += acc[mt][nt][rh * 2] + acc[mt][nt][rh * 2 + 1];
            }
            s += __shfl_xor_sync(0xffffffffu, s, 1);
            s += __shfl_xor_sync(0xffffffffu, s, 2);
            rsum[mt][rh] = s;
        }
    if (tc == 0) {
#pragma unroll
        for (int mt = 0; mt < 2; mt++) {
            red[wnid][wm1 + (mt << 4) + gr]     = rsum[mt][0];
            red[wnid][wm1 + (mt << 4) + gr + 8] = rsum[mt][1];
        }
    }
    __syncthreads();
#pragma unroll
    for (int mt = 0; mt < 2; mt++)
#pragma unroll
        for (int rh = 0; rh < 2; rh++) {
            int row = wm1 + (mt << 4) + gr + rh * 8;
            float inv = 1.f / (red[0][row] + red[1][row] + red[2][row] + red[3][row]);
#pragma unroll
            for (int nt = 0; nt < 8; nt++) {
                int col = wn1 + (nt << 3) + (tc << 1);
                __half2 h = __floats2half2_rn(acc[mt][nt][rh * 2] * inv,
                                              acc[mt][nt][rh * 2 + 1] * inv);
                *(__half2*)(smc + ATTN + row * ROWB + col * 2) = h;
            }
        }
    __syncthreads();

    // ---- phase 2: agg = attn @ g^T (M=64, N=128, K=256, all smem) ----
    int wm2 = (wid & 1) << 5;
    int wn2 = (wid >> 1) << 5;
    uint32_t aA2 = su + ATTN + (wm2 + (lane & 15)) * ROWB + ((lane >> 4) << 4);
    uint32_t bA2 = su + GOFF + (wn2 + (lane & 7) + ((lane >> 4) << 3)) * ROWB
                 + (((lane >> 3) & 1) << 4);

    float a2[2][4][4] = {};
#pragma unroll
    for (int k = 0; k < 16; k++) {
        uint32_t ko = (uint32_t)k << 5;
        uint32_t fa[2][4];
        LDSM4(fa[0][0], fa[0][1], fa[0][2], fa[0][3], aA2 + ko);
        LDSM4(fa[1][0], fa[1][1], fa[1][2], fa[1][3], aA2 + ko + 16 * ROWB);
#pragma unroll
        for (int p = 0; p < 2; p++) {
            uint32_t b0, b1, b2, b3;
            LDSM4(b0, b1, b2, b3, bA2 + ko + p * 16 * ROWB);
            mma_f16(a2[0][2 * p],     fa[0][0], fa[0][1], fa[0][2], fa[0][3], b0, b1);
            mma_f16(a2[1][2 * p],     fa[1][0], fa[1][1], fa[1][2], fa[1][3], b0, b1);
            mma_f16(a2[0][2 * p + 1], fa[0][0], fa[0][1], fa[0][2], fa[0][3], b2, b3);
            mma_f16(a2[1][2 * p + 1], fa[1][0], fa[1][1], fa[1][2], fa[1][3], b2, b3);
        }
    }

    __half* ab = agg + (long)b * 32768;
#pragma unroll
    for (int mt = 0; mt < 2; mt++) {
        int i0 = m0 + wm2 + (mt << 4) + gr;
#pragma unroll
        for (int nt = 0; nt < 4; nt++) {
            int cc = wn2 + (nt << 3) + (tc << 1);
            *(__half2*)(ab + (long)i0 * 128 + cc)       = __floats2half2_rn(a2[mt][nt][0], a2[mt][nt][1]);
            *(__half2*)(ab + (long)(i0 + 8) * 128 + cc) = __floats2half2_rn(a2[mt][nt][2], a2[mt][nt][3]);
        }
    }
}

// -------------------- launch --------------------
#define SMEMH  (4 * 20480)                          // 81920 B
#define SMEMA  (4 * 25600 + 64 * 528 + 128 * 528)   // 203776 B

extern "C" void kernel_launch(void* const* d_in, const int* in_sizes, int n_in,
                              void* d_out, int out_size) {
    (void)in_sizes; (void)n_in; (void)out_size;
    const float* x  = (const float*)d_in[0];
    const float* tw = (const float*)d_in[1];
    const float* tb = (const float*)d_in[2];
    const float* pw = (const float*)d_in[3];
    const float* pb = (const float*)d_in[4];
    const float* gw = (const float*)d_in[5];
    const float* gb = (const float*)d_in[6];
    const float* ow = (const float*)d_in[7];
    const float* ob = (const float*)d_in[8];
    float* out = (float*)d_out;

    float *btp;
    __half *xpt, *xpc, *Wch, *gwh, *owh, *proj, *gg, *agg;
    cudaGetSymbolAddress((void**)&xpt,  g_xpt);
    cudaGetSymbolAddress((void**)&xpc,  g_xpc);
    cudaGetSymbolAddress((void**)&Wch,  g_Wch);
    cudaGetSymbolAddress((void**)&gwh,  g_gwh);
    cudaGetSymbolAddress((void**)&owh,  g_owh);
    cudaGetSymbolAddress((void**)&btp,  g_btp);
    cudaGetSymbolAddress((void**)&proj, g_proj);
    cudaGetSymbolAddress((void**)&gg,   g_g);
    cudaGetSymbolAddress((void**)&agg,  g_agg);

    cudaFuncSetAttribute(hgemm_k<1>, cudaFuncAttributeMaxDynamicSharedMemorySize, SMEMH);
    cudaFuncSetAttribute(hgemm_k<2>, cudaFuncAttributeMaxDynamicSharedMemorySize, SMEMH);
    cudaFuncSetAttribute(hgemm_k<3>, cudaFuncAttributeMaxDynamicSharedMemorySize, SMEMH);
    cudaFuncSetAttribute(attn_kernel, cudaFuncAttributeMaxDynamicSharedMemorySize, SMEMA);

    pool_prep_kernel<<<1024, 256>>>(x, tw, tb, pw, pb, gw, ow);

    // proj[tok][r] = xpt @ Wch^T + btp[n] : M=256, N=256, K=256
    hgemm_k<1><<<dim3(2, 2, NB), 256, SMEMH>>>(
        xpt, Wch, proj, 256, 256, 256, 256, 65536L, 0L, 131072L, btp, nullptr, nullptr);

    // g[cc][j] = gwh @ xpt^T + gb[m] : M=128, N=256, K=256
    hgemm_k<2><<<dim3(2, 1, NB), 256, SMEMH>>>(
        gwh, xpt, gg, 256, 256, 256, 256, 0L, 65536L, 65536L, gb, nullptr, nullptr);

    // fused attention: logits + softmax + agg
    attn_kernel<<<dim3(4, NB), 256, SMEMA>>>(proj, gg, agg);

    // out[C][tok] = owh @ agg^T + ob[m] + xpc-resid, upsample -> d_out : M=256, N=256, K=128
    hgemm_k<3><<<dim3(2, 2, NB), 256, SMEMH>>>(
        owh, agg, nullptr, 128, 128, 0, 128, 0L, 32768L, 0L, ob, xpc, out);
}

// round 17
// speedup vs baseline: 1.1188x; 1.1188x over previous
#include <cuda_runtime.h>
#include <cuda_fp16.h>
#include <cstdint>

#define NB   64
#define NC   256
#define NCI  128
#define NTOK 256
#define NH   64

// -------------------- device scratch --------------------
__device__ __half g_xpt [NB * NTOK * NC];   // pooled fp16 [b][tok][c]  (GEMM operand)
__device__ __half g_xpc [NB * NC * NTOK];   // pooled fp16 [b][c][tok]  (residual)
__device__ __half g_Wch [256 * NC];         // theta|phi weights fp16 [r][c]
__device__ __half g_gwh [NCI * NC];         // fp16 [cc][c]
__device__ __half g_owh [NC * NCI];         // fp16 [C][cc]
__device__ float  g_btp [256];              // theta_b|phi_b fp32
__device__ __half g_proj[NB * NTOK * 256];  // [tok][r] (theta 0-127 | phi 128-255)
__device__ __half g_g   [NB * NCI * NTOK];  // [cc][j]
__device__ __half g_agg [NB * NTOK * NCI];  // [i][cc]

// -------------------- helpers --------------------
__device__ __forceinline__ void mma_f16(float (&c)[4],
                                        uint32_t a0, uint32_t a1, uint32_t a2, uint32_t a3,
                                        uint32_t b0, uint32_t b1) {
    asm volatile(
        "mma.sync.aligned.m16n8k16.row.col.f32.f16.f16.f32 "
        "{%0,%1,%2,%3},{%4,%5,%6,%7},{%8,%9},{%0,%1,%2,%3};\n"
        : "+f"(c[0]), "+f"(c[1]), "+f"(c[2]), "+f"(c[3])
        : "r"(a0), "r"(a1), "r"(a2), "r"(a3), "r"(b0), "r"(b1));
}
#define LDSM4(r0, r1, r2, r3, a) \
    asm volatile("ldmatrix.sync.aligned.m8n8.x4.shared.b16 {%0,%1,%2,%3}, [%4];" \
                 : "=r"(r0), "=r"(r1), "=r"(r2), "=r"(r3) : "r"(a))
#define CPA(dst, src) asm volatile("cp.async.cg.shared.global [%0], [%1], 16;" :: "r"(dst), "l"(src))
#define CPC()         asm volatile("cp.async.commit_group;")
#define CPW(n)        asm volatile("cp.async.wait_group %0;" :: "n"(n))

// -------------------- fused pool + weight prep (16 channels/CTA, grid 1024+512) ------
__global__ void __launch_bounds__(256) pool_prep_kernel(
    const float* __restrict__ x,
    const float* __restrict__ tw, const float* __restrict__ tb,
    const float* __restrict__ pw, const float* __restrict__ pb,
    const float* __restrict__ gw, const float* __restrict__ ow) {
    if (blockIdx.x < 1024) {
        __shared__ float tile[16][257];
        int b = blockIdx.x >> 4, c0 = (blockIdx.x & 15) << 4;
        int t = threadIdx.x;
        int ph = t >> 4, pw2 = t & 15;
        for (int ci = 0; ci < 16; ci++) {
            int c = c0 + ci;
            const float* base = x + (((long)b * NC + c) * NH + ph * 4) * NH + pw2 * 4;
            float4 v0 = *(const float4*)(base);
            float4 v1 = *(const float4*)(base + NH);
            float4 v2 = *(const float4*)(base + 2 * NH);
            float4 v3 = *(const float4*)(base + 3 * NH);
            float s = ((v0.x + v0.y + v0.z + v0.w) + (v1.x + v1.y + v1.z + v1.w)
                     + (v2.x + v2.y + v2.z + v2.w) + (v3.x + v3.y + v3.z + v3.w)) * 0.0625f;
            tile[ci][t] = s;
            g_xpc[((long)b * NC + c) * NTOK + t] = __float2half_rn(s);
        }
        __syncthreads();
#pragma unroll
        for (int rep = 0; rep < 4; rep++) {
            int u = rep * 256 + t;
            int tok = u >> 2, cq = (u & 3) << 2;
            __half2 h0 = __floats2half2_rn(tile[cq][tok],     tile[cq + 1][tok]);
            __half2 h1 = __floats2half2_rn(tile[cq + 2][tok], tile[cq + 3][tok]);
            __half2* dst = (__half2*)&g_xpt[((long)b * NTOK + tok) * NC + c0 + cq];
            dst[0] = h0; dst[1] = h1;
        }
    } else {
        int idx = (blockIdx.x - 1024) * 256 + threadIdx.x;
        if (idx < 65536) {
            int r = idx >> 8;
            g_Wch[idx] = __float2half_rn((r < 128) ? tw[idx] : pw[idx - 32768]);
            if (idx < 256) g_btp[idx] = (idx < 128) ? tb[idx] : pb[idx - 128];
        } else if (idx < 98304) {
            int j = idx - 65536;
            g_gwh[j] = __float2half_rn(gw[j]);
        } else {
            int j = idx - 98304;
            g_owh[j] = __float2half_rn(ow[j]);
        }
    }
}

// -------------------- fp16 GEMM core: BM=64, BN=128, BK=32, ldmatrix, 3 CTAs/SM -----
// C[m][n] = sum_k A[m][k]*B[n][k]. 8 warps as 2(M)x4(N), warp tile 32x32 (mt=2, nt=4).
// EPI 1: fp16 +bias[n]  2: fp16 +bias[m]
// EPI 3: fp32 +bias[m] + resid(fp16 [c][tok]), nearest 4x4 upsample -> dout
template<int EPI>
__device__ __forceinline__ void hgemm_core(
    const __half* __restrict__ A, const __half* __restrict__ B, void* __restrict__ Cg,
    int lda, int ldb, int ldc, int K, int m0, int n0, int b,
    const float* __restrict__ bias, const __half* __restrict__ residh,
    float* __restrict__ dout, __half* smem)
{
    constexpr int SKB  = 80;                 // bytes per smem row (32 fp16 + pad)
    constexpr int AB   = 64 * SKB;           // 5120
    constexpr int BBY  = 128 * SKB;          // 10240
    constexpr int STGB = AB + BBY;           // 15360 per stage

    uint32_t su = (uint32_t)__cvta_generic_to_shared(smem);
    int tid = threadIdx.x;
    int lane = tid & 31, wid = tid >> 5;
    int wm = (wid & 1) << 5;                 // 0,32
    int wn = (wid >> 1) << 5;                // 0,32,64,96
    int gr = lane >> 2, tc = lane & 3;

    float acc[2][4][4] = {};
    int nk = K >> 5;

    uint32_t aAddr = su + (wm + (lane & 15)) * SKB + ((lane >> 4) << 4);
    uint32_t bAddr = su + AB + (wn + (lane & 7) + ((lane >> 4) << 3)) * SKB
                   + (((lane >> 3) & 1) << 4);

    int rS = tid >> 2, cS = tid & 3;         // A: 64 rows x 4 chunks = 1 CPA/thread
    auto issue = [&](int slot, int t) {
        int k0 = t << 5;
        uint32_t base = su + slot * STGB;
        CPA(base + rS * SKB + cS * 16, A + (long)(m0 + rS) * lda + k0 + cS * 8);
        uint32_t bb = base + AB;
#pragma unroll
        for (int i = 0; i < 2; i++) {        // B: 128 rows x 4 chunks = 2 CPA/thread
            int u = tid + i * 256;
            int rB = u >> 2, cb = u & 3;
            CPA(bb + rB * SKB + cb * 16, B + (long)(n0 + rB) * ldb + k0 + cb * 8);
        }
        CPC();
    };

    issue(0, 0); issue(1, 1); issue(2, 2);

    for (int t = 0; t < nk; t++) {
        CPW(2);
        __syncthreads();
        if (t + 3 < nk) issue((t + 3) & 3, t + 3);
        else            CPC();
        uint32_t so = (uint32_t)(t & 3) * STGB;
#pragma unroll
        for (int ks = 0; ks < 2; ks++) {
            uint32_t ko = ks << 5;
            uint32_t fa[2][4];
            LDSM4(fa[0][0], fa[0][1], fa[0][2], fa[0][3], aAddr + so + ko);
            LDSM4(fa[1][0], fa[1][1], fa[1][2], fa[1][3], aAddr + so + ko + 16 * SKB);
#pragma unroll
            for (int p = 0; p < 2; p++) {    // nt pairs {0,1},{2,3}
                uint32_t b0, b1, b2, b3;
                LDSM4(b0, b1, b2, b3, bAddr + so + ko + p * 16 * SKB);
                mma_f16(acc[0][2 * p],     fa[0][0], fa[0][1], fa[0][2], fa[0][3], b0, b1);
                mma_f16(acc[1][2 * p],     fa[1][0], fa[1][1], fa[1][2], fa[1][3], b0, b1);
                mma_f16(acc[0][2 * p + 1], fa[0][0], fa[0][1], fa[0][2], fa[0][3], b2, b3);
                mma_f16(acc[1][2 * p + 1], fa[1][0], fa[1][1], fa[1][2], fa[1][3], b2, b3);
            }
        }
    }

    if (EPI == 1 || EPI == 2) {
        __half* Cb = (__half*)Cg;
#pragma unroll
        for (int mt = 0; mt < 2; mt++) {
            int r0 = m0 + wm + (mt << 4) + gr;
            float bm0 = 0.f, bm1 = 0.f;
            if (EPI == 2) { bm0 = bias[r0]; bm1 = bias[r0 + 8]; }
#pragma unroll
            for (int nt = 0; nt < 4; nt++) {
                int cn = n0 + wn + (nt << 3) + (tc << 1);
                float bn0 = 0.f, bn1 = 0.f;
                if (EPI == 1) { bn0 = bias[cn]; bn1 = bias[cn + 1]; }
                *(__half2*)(Cb + (long)r0 * ldc + cn) =
                    __floats2half2_rn(acc[mt][nt][0] + bm0 + bn0, acc[mt][nt][1] + bm0 + bn1);
                *(__half2*)(Cb + (long)(r0 + 8) * ldc + cn) =
                    __floats2half2_rn(acc[mt][nt][2] + bm1 + bn0, acc[mt][nt][3] + bm1 + bn1);
            }
        }
    } else {
#pragma unroll
        for (int mt = 0; mt < 2; mt++) {
#pragma unroll
            for (int rr = 0; rr < 2; rr++) {
                int c = m0 + wm + (mt << 4) + gr + (rr << 3);
                float bi = bias[c];
                const __half* rrow = residh + ((long)b * NC + c) * NTOK;
                float* orow = dout + ((long)b * NC + c) * (NH * NH);
#pragma unroll
                for (int nt = 0; nt < 4; nt++) {
                    int tok0 = n0 + wn + (nt << 3) + (tc << 1);
                    __half2 rh = *(const __half2*)(rrow + tok0);
                    float r2[2] = {__half2float(rh.x), __half2float(rh.y)};
#pragma unroll
                    for (int jj = 0; jj < 2; jj++) {
                        int tok = tok0 + jj;
                        float v = acc[mt][nt][rr * 2 + jj] + bi + r2[jj];
                        int ph = tok >> 4, pw = tok & 15;
                        float* o = orow + (ph * 4) * NH + pw * 4;
                        float4 f = make_float4(v, v, v, v);
                        *(float4*)(o)          = f;
                        *(float4*)(o + NH)     = f;
                        *(float4*)(o + 2 * NH) = f;
                        *(float4*)(o + 3 * NH) = f;
                    }
                }
            }
        }
    }
}

template<int EPI>
__global__ void __launch_bounds__(256, 3) hgemm_k(
    const __half* __restrict__ Ag, const __half* __restrict__ Bg, void* __restrict__ Cg,
    int lda, int ldb, int ldc, int K,
    long aB, long bB, long cB,
    const float* __restrict__ bias, const __half* __restrict__ residh, float* __restrict__ dout)
{
    extern __shared__ __half smem[];
    int b = blockIdx.z;
    char* Cp = (char*)Cg + (long)b * cB;
    hgemm_core<EPI>(Ag + (long)b * aB, Bg + (long)b * bB, (void*)Cp,
                    lda, ldb, ldc, K, blockIdx.y << 6, blockIdx.x << 7, b,
                    bias, residh, dout, smem);
}

// -------------------- fused attention: logits + softmax + agg (unchanged) ------------
__global__ void __launch_bounds__(256) attn_kernel(
    const __half* __restrict__ proj, const __half* __restrict__ gg,
    __half* __restrict__ agg)
{
    constexpr int SKB  = 80;
    constexpr int A1B  = 64 * SKB;
    constexpr int B1B  = 256 * SKB;
    constexpr int STG1 = A1B + B1B;           // 25600
    constexpr int ATTN = 4 * STG1;            // 102400
    constexpr int ROWB = 528;
    constexpr int GOFF = ATTN + 64 * ROWB;

    extern __shared__ __half smem[];
    __shared__ float red[4][64];
    uint32_t su = (uint32_t)__cvta_generic_to_shared(smem);
    char* smc = (char*)smem;

    int b = blockIdx.y;
    int m0 = blockIdx.x << 6;
    const __half* theta = proj + (long)b * 65536;
    const __half* phi   = theta + 128;
    const __half* gb    = gg + (long)b * 32768;

    int tid = threadIdx.x, lane = tid & 31, wid = tid >> 5;
    int gr = lane >> 2, tc = lane & 3;
    int wm1 = (wid & 1) << 5;
    int wn1 = (wid >> 1) << 6;
    int wnid = wid >> 1;

    int rA = tid >> 2, cA = tid & 3;
#pragma unroll
    for (int t = 0; t < 4; t++) {
        uint32_t base = su + t * STG1;
        CPA(base + rA * SKB + cA * 16, theta + (long)(m0 + rA) * 256 + t * 32 + cA * 8);
#pragma unroll
        for (int it = 0; it < 4; it++) {
            int row = rA + it * 64;
            CPA(base + A1B + row * SKB + cA * 16, phi + (long)row * 256 + t * 32 + cA * 8);
        }
#pragma unroll
        for (int k = 0; k < 4; k++) {
            int u = tid + k * 256;
            int grow = t * 32 + (u >> 5);
            int gch = u & 31;
            CPA(su + GOFF + grow * ROWB + gch * 16, gb + (long)grow * 256 + gch * 8);
        }
        CPC();
    }

    uint32_t aA1 = su + (wm1 + (lane & 15)) * SKB + ((lane >> 4) << 4);
    uint32_t bA1 = su + A1B + (wn1 + (lane & 7) + ((lane >> 4) << 3)) * SKB
                 + (((lane >> 3) & 1) << 4);

    float acc[2][8][4] = {};
#pragma unroll
    for (int t = 0; t < 4; t++) {
        if (t == 0)      { CPW(3); }
        else if (t == 1) { CPW(2); }
        else if (t == 2) { CPW(1); }
        else             { CPW(0); }
        __syncthreads();
        uint32_t so = (uint32_t)t * STG1;
#pragma unroll
        for (int ks = 0; ks < 2; ks++) {
            uint32_t ko = ks << 5;
            uint32_t fa[2][4];
            LDSM4(fa[0][0], fa[0][1], fa[0][2], fa[0][3], aA1 + so + ko);
            LDSM4(fa[1][0], fa[1][1], fa[1][2], fa[1][3], aA1 + so + ko + 16 * SKB);
#pragma unroll
            for (int p = 0; p < 4; p++) {
                uint32_t b0, b1, b2, b3;
                LDSM4(b0, b1, b2, b3, bA1 + so + ko + p * 16 * SKB);
                mma_f16(acc[0][2 * p],     fa[0][0], fa[0][1], fa[0][2], fa[0][3], b0, b1);
                mma_f16(acc[1][2 * p],     fa[1][0], fa[1][1], fa[1][2], fa[1][3], b0, b1);
                mma_f16(acc[0][2 * p + 1], fa[0][0], fa[0][1], fa[0][2], fa[0][3], b2, b3);
                mma_f16(acc[1][2 * p + 1], fa[1][0], fa[1][1], fa[1][2], fa[1][3], b2, b3);
            }
        }
    }

    // ---- softmax over j ----
    float rmx[2][2];
#pragma unroll
    for (int mt = 0; mt < 2; mt++)
#pragma unroll
        for (int rh = 0; rh < 2; rh++) {
            float m = -1e30f;
#pragma unroll
            for (int nt = 0; nt < 8; nt++)
                m = fmaxf(m, fmaxf(acc[mt][nt][rh * 2], acc[mt][nt][rh * 2 + 1]));
            m = fmaxf(m, __shfl_xor_sync(0xffffffffu, m, 1));
            m = fmaxf(m, __shfl_xor_sync(0xffffffffu, m, 2));
            rmx[mt][rh] = m;
        }
    if (tc == 0) {
#pragma unroll
        for (int mt = 0; mt < 2; mt++) {
            red[wnid][wm1 + (mt << 4) + gr]     = rmx[mt][0];
            red[wnid][wm1 + (mt << 4) + gr + 8] = rmx[mt][1];
        }
    }
    __syncthreads();
#pragma unroll
    for (int mt = 0; mt < 2; mt++)
#pragma unroll
        for (int rh = 0; rh < 2; rh++) {
            int row = wm1 + (mt << 4) + gr + rh * 8;
            rmx[mt][rh] = fmaxf(fmaxf(red[0][row], red[1][row]),
                                fmaxf(red[2][row], red[3][row]));
        }
    __syncthreads();

    float rsum[2][2];
#pragma unroll
    for (int mt = 0; mt < 2; mt++)
#pragma unroll
        for (int rh = 0; rh < 2; rh++) {
            float s = 0.f;
#pragma unroll
            for (int nt = 0; nt < 8; nt++) {
                acc[mt][nt][rh * 2]     = __expf(acc[mt][nt][rh * 2]     - rmx[mt][rh]);
                acc[mt][nt][rh * 2 + 1] = __expf(acc[mt][nt][rh * 2 + 1] - rmx[mt][rh]);
                s += acc[mt][nt][rh * 2] + acc[mt][nt][rh * 2 + 1];
            }
            s += __shfl_xor_sync(0xffffffffu, s, 1);
            s += __shfl_xor_sync(0xffffffffu, s, 2);
            rsum[mt][rh] = s;
        }
    if (tc == 0) {
#pragma unroll
        for (int mt = 0; mt < 2; mt++) {
            red[wnid][wm1 + (mt << 4) + gr]     = rsum[mt][0];
            red[wnid][wm1 + (mt << 4) + gr + 8] = rsum[mt][1];
        }
    }
    __syncthreads();
#pragma unroll
    for (int mt = 0; mt < 2; mt++)
#pragma unroll
        for (int rh = 0; rh < 2; rh++) {
            int row = wm1 + (mt << 4) + gr + rh * 8;
            float inv = 1.f / (red[0][row] + red[1][row] + red[2][row] + red[3][row]);
#pragma unroll
            for (int nt = 0; nt < 8; nt++) {
                int col = wn1 + (nt << 3) + (tc << 1);
                __half2 h = __floats2half2_rn(acc[mt][nt][rh * 2] * inv,
                                              acc[mt][nt][rh * 2 + 1] * inv);
                *(__half2*)(smc + ATTN + row * ROWB + col * 2) = h;
            }
        }
    __syncthreads();

    // ---- phase 2: agg = attn @ g^T ----
    int wm2 = (wid & 1) << 5;
    int wn2 = (wid >> 1) << 5;
    uint32_t aA2 = su + ATTN + (wm2 + (lane & 15)) * ROWB + ((lane >> 4) << 4);
    uint32_t bA2 = su + GOFF + (wn2 + (lane & 7) + ((lane >> 4) << 3)) * ROWB
                 + (((lane >> 3) & 1) << 4);

    float a2[2][4][4] = {};
#pragma unroll
    for (int k = 0; k < 16; k++) {
        uint32_t ko = (uint32_t)k << 5;
        uint32_t fa[2][4];
        LDSM4(fa[0][0], fa[0][1], fa[0][2], fa[0][3], aA2 + ko);
        LDSM4(fa[1][0], fa[1][1], fa[1][2], fa[1][3], aA2 + ko + 16 * ROWB);
#pragma unroll
        for (int p = 0; p < 2; p++) {
            uint32_t b0, b1, b2, b3;
            LDSM4(b0, b1, b2, b3, bA2 + ko + p * 16 * ROWB);
            mma_f16(a2[0][2 * p],     fa[0][0], fa[0][1], fa[0][2], fa[0][3], b0, b1);
            mma_f16(a2[1][2 * p],     fa[1][0], fa[1][1], fa[1][2], fa[1][3], b0, b1);
            mma_f16(a2[0][2 * p + 1], fa[0][0], fa[0][1], fa[0][2], fa[0][3], b2, b3);
            mma_f16(a2[1][2 * p + 1], fa[1][0], fa[1][1], fa[1][2], fa[1][3], b2, b3);
        }
    }

    __half* ab = agg + (long)b * 32768;
#pragma unroll
    for (int mt = 0; mt < 2; mt++) {
        int i0 = m0 + wm2 + (mt << 4) + gr;
#pragma unroll
        for (int nt = 0; nt < 4; nt++) {
            int cc = wn2 + (nt << 3) + (tc << 1);
            *(__half2*)(ab + (long)i0 * 128 + cc)       = __floats2half2_rn(a2[mt][nt][0], a2[mt][nt][1]);
            *(__half2*)(ab + (long)(i0 + 8) * 128 + cc) = __floats2half2_rn(a2[mt][nt][2], a2[mt][nt][3]);
        }
    }
}

// -------------------- launch --------------------
#define SMEMH  (4 * 15360)                          // 61440 B
#define SMEMA  (4 * 25600 + 64 * 528 + 128 * 528)   // 203776 B

extern "C" void kernel_launch(void* const* d_in, const int* in_sizes, int n_in,
                              void* d_out, int out_size) {
    (void)in_sizes; (void)n_in; (void)out_size;
    const float* x  = (const float*)d_in[0];
    const float* tw = (const float*)d_in[1];
    const float* tb = (const float*)d_in[2];
    const float* pw = (const float*)d_in[3];
    const float* pb = (const float*)d_in[4];
    const float* gw = (const float*)d_in[5];
    const float* gb = (const float*)d_in[6];
    const float* ow = (const float*)d_in[7];
    const float* ob = (const float*)d_in[8];
    float* out = (float*)d_out;

    float *btp;
    __half *xpt, *xpc, *Wch, *gwh, *owh, *proj, *gg, *agg;
    cudaGetSymbolAddress((void**)&xpt,  g_xpt);
    cudaGetSymbolAddress((void**)&xpc,  g_xpc);
    cudaGetSymbolAddress((void**)&Wch,  g_Wch);
    cudaGetSymbolAddress((void**)&gwh,  g_gwh);
    cudaGetSymbolAddress((void**)&owh,  g_owh);
    cudaGetSymbolAddress((void**)&btp,  g_btp);
    cudaGetSymbolAddress((void**)&proj, g_proj);
    cudaGetSymbolAddress((void**)&gg,   g_g);
    cudaGetSymbolAddress((void**)&agg,  g_agg);

    cudaFuncSetAttribute(hgemm_k<1>, cudaFuncAttributeMaxDynamicSharedMemorySize, SMEMH);
    cudaFuncSetAttribute(hgemm_k<2>, cudaFuncAttributeMaxDynamicSharedMemorySize, SMEMH);
    cudaFuncSetAttribute(hgemm_k<3>, cudaFuncAttributeMaxDynamicSharedMemorySize, SMEMH);
    cudaFuncSetAttribute(attn_kernel, cudaFuncAttributeMaxDynamicSharedMemorySize, SMEMA);

    pool_prep_kernel<<<1536, 256>>>(x, tw, tb, pw, pb, gw, ow);

    // proj[tok][r] = xpt @ Wch^T + btp[n] : M=256, N=256, K=256 — grid 512
    hgemm_k<1><<<dim3(2, 4, NB), 256, SMEMH>>>(
        xpt, Wch, proj, 256, 256, 256, 256, 65536L, 0L, 131072L, btp, nullptr, nullptr);

    // g[cc][j] = gwh @ xpt^T + gb[m] : M=128, N=256, K=256 — grid 256
    hgemm_k<2><<<dim3(2, 2, NB), 256, SMEMH>>>(
        gwh, xpt, gg, 256, 256, 256, 256, 0L, 65536L, 65536L, gb, nullptr, nullptr);

    // fused attention
    attn_kernel<<<dim3(4, NB), 256, SMEMA>>>(proj, gg, agg);

    // out[C][tok] = owh @ agg^T + ob[m] + xpc-resid, upsample -> d_out — grid 512
    hgemm_k<3><<<dim3(2, 4, NB), 256, SMEMH>>>(
        owh, agg, nullptr, 128, 128, 0, 128, 0L, 32768L, 0L, ob, xpc, out);
}